// round 1
// baseline (speedup 1.0000x reference)
#include <cuda_runtime.h>

#define BATCH 8
#define CC    128
#define NPT   20000
#define SPLIT 50
#define KPS   400            // NPT / SPLIT
#define EPSB  1e-5f
#define NTILES 313           // ceil(20000/64)

typedef unsigned long long u64;

// ---------------- scratch (static device allocations; no cudaMalloc) ----------
__device__ float g_qs   [BATCH*CC*NPT];     // q * scale/temp, post-ReLU
__device__ float g_kpg  [BATCH*CC*NPT];     // relu(BN(k)) + graph_context
__device__ float g_v    [BATCH*CC*NPT];
__device__ float g_part [BATCH*SPLIT*CC*CC];
__device__ float g_attnT[BATCH*CC*CC];      // transposed softmax weights [b][d][c]
__device__ float g_wt   [3*CC*CC];          // transposed, BN-scale-folded weights
__device__ float g_shift[3*CC];
__device__ float g_G    [CC*4];             // graph-context coeffs per output c
__device__ float g_bsum [CC];

// ---------------- packed fp32x2 helpers ---------------------------------------
__device__ __forceinline__ void fma2(u64 &d, u64 a, u64 b) {
    asm("fma.rn.f32x2 %0, %1, %2, %0;" : "+l"(d) : "l"(a), "l"(b));
}
__device__ __forceinline__ u64 dup2(float x) {
    u64 r; asm("mov.b64 %0, {%1, %2};" : "=l"(r) : "f"(x), "f"(x)); return r;
}
__device__ __forceinline__ float2 unpk(u64 v) {
    float2 r; asm("mov.b64 {%0, %1}, %2;" : "=f"(r.x), "=f"(r.y) : "l"(v)); return r;
}

#define FMA_ROW(i, a, b0, b1, b2, b3) \
    { fma2(acc[i][0], a, b0); fma2(acc[i][1], a, b1); \
      fma2(acc[i][2], a, b2); fma2(acc[i][3], a, b3); }

// ---------------- K0: fold BN into transposed weights --------------------------
__global__ void setup_kernel(
    const float* __restrict__ Wq, const float* __restrict__ gq, const float* __restrict__ bq,
    const float* __restrict__ mq, const float* __restrict__ vq,
    const float* __restrict__ Wk, const float* __restrict__ gk, const float* __restrict__ bk,
    const float* __restrict__ mk, const float* __restrict__ vk,
    const float* __restrict__ Wv, const float* __restrict__ gv, const float* __restrict__ bv,
    const float* __restrict__ mv, const float* __restrict__ vv,
    const float* __restrict__ Wg1, const float* __restrict__ bg1,
    const float* __restrict__ Wg2, const float* __restrict__ bg2)
{
    int idx = blockIdx.x * 256 + threadIdx.x;
    const float invtemp = rsqrtf(128.0f);
    if (idx < 3*CC*CC) {
        int p = idx / (CC*CC);
        int r = idx - p*(CC*CC);
        int k = r >> 7, c = r & 127;
        const float* W  = (p==0 ? Wq : (p==1 ? Wk : Wv));
        const float* g  = (p==0 ? gq : (p==1 ? gk : gv));
        const float* vr = (p==0 ? vq : (p==1 ? vk : vv));
        float scale = g[c] * rsqrtf(vr[c] + EPSB);
        if (p == 0) scale *= invtemp;
        g_wt[idx] = W[c*CC + k] * scale;        // Wt[p][k][c]
    }
    if (idx < 3*CC) {
        int p = idx >> 7, c = idx & 127;
        const float* g  = (p==0 ? gq : (p==1 ? gk : gv));
        const float* vr = (p==0 ? vq : (p==1 ? vk : vv));
        const float* bb = (p==0 ? bq : (p==1 ? bk : bv));
        const float* mm = (p==0 ? mq : (p==1 ? mk : mv));
        float scale = g[c] * rsqrtf(vr[c] + EPSB);
        float sh = bb[c] - mm[c]*scale;
        if (p == 0) sh *= invtemp;
        g_shift[idx] = sh;
    }
    if (idx < CC) {
        g_G[idx*4+0] = Wg1[idx*2+0];
        g_G[idx*4+1] = Wg1[idx*2+1];
        g_G[idx*4+2] = Wg2[idx*2+0];
        g_G[idx*4+3] = Wg2[idx*2+1];
        g_bsum[idx]  = bg1[idx] + bg2[idx];
    }
}

// ---------------- K1: fused q/k/v projection + BN + ReLU + graph-context -------
// Tile: 128 c x 64 n, 256 threads, micro-tile 4c x 8n (f32x2-packed over n)
__global__ __launch_bounds__(256) void proj_kernel(const float* __restrict__ pc_all,
                                                   const float* __restrict__ x_all)
{
    __shared__ float pcs[CC][64];     // [c'][n]
    __shared__ float ws[8][CC];       // Wt chunk [k][c]
    __shared__ float xs[4][64];
    __shared__ float shs[3][CC];
    __shared__ float Gs[CC][4];
    __shared__ float bsums[CC];

    int b  = blockIdx.y;
    int n0 = blockIdx.x * 64;
    int tid = threadIdx.x;
    int tx = tid & 7, ty = tid >> 3;
    int tx8 = tx*8, ty4 = ty*4;

    const float* pcb = pc_all + (size_t)b*CC*NPT;

    #pragma unroll
    for (int it = 0; it < 8; it++) {
        int idx = tid + it*256;                // 2048 float4 loads
        int r = idx >> 4, v4 = idx & 15;
        int n = n0 + v4*4;
        float4 val = make_float4(0.f, 0.f, 0.f, 0.f);
        if (n < NPT) val = *(const float4*)(pcb + (size_t)r*NPT + n);
        *(float4*)&pcs[r][v4*4] = val;
    }
    {
        int ch = tid >> 6, nn = tid & 63;
        int n = n0 + nn;
        xs[ch][nn] = (n < NPT) ? x_all[((size_t)b*4 + ch)*NPT + n] : 0.f;
    }
    if (tid < CC) {
        shs[0][tid] = g_shift[tid];
        shs[1][tid] = g_shift[CC + tid];
        shs[2][tid] = g_shift[2*CC + tid];
        bsums[tid]  = g_bsum[tid];
        *(float4*)&Gs[tid][0] = *(const float4*)&g_G[tid*4];
    }

    for (int p = 0; p < 3; p++) {
        u64 acc[4][4];
        #pragma unroll
        for (int i = 0; i < 4; i++)
            #pragma unroll
            for (int j = 0; j < 4; j++) acc[i][j] = 0ull;

        const float* wt = g_wt + p*CC*CC;
        for (int kc = 0; kc < CC; kc += 8) {
            __syncthreads();
            {
                int k = tid >> 5, c4 = tid & 31;
                *(float4*)&ws[k][c4*4] = *(const float4*)(wt + (kc+k)*CC + c4*4);
            }
            __syncthreads();
            #pragma unroll
            for (int kk = 0; kk < 8; kk++) {
                float4 av = *(const float4*)&ws[kk][ty4];
                u64 a0 = dup2(av.x), a1 = dup2(av.y), a2 = dup2(av.z), a3 = dup2(av.w);
                const float* bb = &pcs[kc+kk][tx8];
                ulonglong2 p0 = *(const ulonglong2*)bb;
                ulonglong2 p1 = *(const ulonglong2*)(bb + 4);
                u64 b0 = p0.x, b1 = p0.y, b2 = p1.x, b3 = p1.y;
                FMA_ROW(0, a0, b0, b1, b2, b3)
                FMA_ROW(1, a1, b0, b1, b2, b3)
                FMA_ROW(2, a2, b0, b1, b2, b3)
                FMA_ROW(3, a3, b0, b1, b2, b3)
            }
        }

        float* dst = (p==0 ? g_qs : (p==1 ? g_kpg : g_v)) + (size_t)b*CC*NPT;
        int n = n0 + tx8;
        #pragma unroll
        for (int i = 0; i < 4; i++) {
            int c = ty4 + i;
            float sh = shs[p][c];
            float o[8];
            float2 t;
            t = unpk(acc[i][0]); o[0] = t.x; o[1] = t.y;
            t = unpk(acc[i][1]); o[2] = t.x; o[3] = t.y;
            t = unpk(acc[i][2]); o[4] = t.x; o[5] = t.y;
            t = unpk(acc[i][3]); o[6] = t.x; o[7] = t.y;
            #pragma unroll
            for (int j = 0; j < 8; j++) o[j] = fmaxf(o[j] + sh, 0.f);
            if (p == 1) {
                float gg0 = Gs[c][0], gg1 = Gs[c][1], gg2 = Gs[c][2], gg3 = Gs[c][3];
                float bs = bsums[c];
                #pragma unroll
                for (int j = 0; j < 8; j++) {
                    int nn = tx8 + j;
                    o[j] += fmaf(gg0, xs[0][nn],
                            fmaf(gg1, xs[1][nn],
                            fmaf(gg2, xs[2][nn],
                            fmaf(gg3, xs[3][nn], bs))));
                }
            }
            if (n < NPT) {
                *(float4*)(dst + (size_t)c*NPT + n)     = make_float4(o[0], o[1], o[2], o[3]);
                *(float4*)(dst + (size_t)c*NPT + n + 4) = make_float4(o[4], o[5], o[6], o[7]);
            }
        }
    }
}

// ---------------- K2: logits partials (split-K over n) -------------------------
// Tile: 128 c x 64 d, K-chunk 16, micro 4c x 8d
__global__ __launch_bounds__(256) void logits_kernel()
{
    __shared__ float qss[16][132];    // [k][c]
    __shared__ float kss[16][68];     // [k][d]

    int s  = blockIdx.x;
    int d0 = blockIdx.y * 64;
    int b  = blockIdx.z;
    int tid = threadIdx.x;
    int tx = tid & 7, ty = tid >> 3;
    int tx8 = tx*8, ty4 = ty*4;

    const float* qb = g_qs  + (size_t)b*CC*NPT + s*KPS;
    const float* kb = g_kpg + (size_t)b*CC*NPT + (size_t)d0*NPT + s*KPS;

    u64 acc[4][4];
    #pragma unroll
    for (int i = 0; i < 4; i++)
        #pragma unroll
        for (int j = 0; j < 4; j++) acc[i][j] = 0ull;

    for (int ch = 0; ch < KPS; ch += 16) {
        __syncthreads();
        #pragma unroll
        for (int it = 0; it < 2; it++) {
            int idx = tid + it*256;            // 512: 128 rows x 4 vec4
            int c = idx >> 2, kv = idx & 3;
            float4 q4 = *(const float4*)(qb + (size_t)c*NPT + ch + kv*4);
            qss[kv*4+0][c] = q4.x; qss[kv*4+1][c] = q4.y;
            qss[kv*4+2][c] = q4.z; qss[kv*4+3][c] = q4.w;
        }
        {
            int dd = tid >> 2, kv = tid & 3;   // 256: 64 rows x 4 vec4
            float4 k4 = *(const float4*)(kb + (size_t)dd*NPT + ch + kv*4);
            kss[kv*4+0][dd] = k4.x; kss[kv*4+1][dd] = k4.y;
            kss[kv*4+2][dd] = k4.z; kss[kv*4+3][dd] = k4.w;
        }
        __syncthreads();
        #pragma unroll
        for (int kk = 0; kk < 16; kk++) {
            float4 av = *(const float4*)&qss[kk][ty4];
            u64 a0 = dup2(av.x), a1 = dup2(av.y), a2 = dup2(av.z), a3 = dup2(av.w);
            const float* bb = &kss[kk][tx8];
            ulonglong2 p0 = *(const ulonglong2*)bb;
            ulonglong2 p1 = *(const ulonglong2*)(bb + 4);
            u64 b0 = p0.x, b1 = p0.y, b2 = p1.x, b3 = p1.y;
            FMA_ROW(0, a0, b0, b1, b2, b3)
            FMA_ROW(1, a1, b0, b1, b2, b3)
            FMA_ROW(2, a2, b0, b1, b2, b3)
            FMA_ROW(3, a3, b0, b1, b2, b3)
        }
    }

    float* dst = g_part + ((size_t)b*SPLIT + s)*CC*CC + d0;
    #pragma unroll
    for (int i = 0; i < 4; i++) {
        int c = ty4 + i;
        float o[8];
        float2 t;
        t = unpk(acc[i][0]); o[0] = t.x; o[1] = t.y;
        t = unpk(acc[i][1]); o[2] = t.x; o[3] = t.y;
        t = unpk(acc[i][2]); o[4] = t.x; o[5] = t.y;
        t = unpk(acc[i][3]); o[6] = t.x; o[7] = t.y;
        *(float4*)(dst + (size_t)c*CC + tx8)     = make_float4(o[0], o[1], o[2], o[3]);
        *(float4*)(dst + (size_t)c*CC + tx8 + 4) = make_float4(o[4], o[5], o[6], o[7]);
    }
}

// ---------------- K3: reduce partials + softmax (writes transposed attn) -------
__global__ void softmax_kernel()
{
    int c = blockIdx.x, b = blockIdx.y;
    int d = threadIdx.x;              // 128 threads
    const float* p = g_part + ((size_t)b*SPLIT*CC + c)*CC + d;
    float sum = 0.f;
    #pragma unroll 5
    for (int s = 0; s < SPLIT; s++) sum += p[(size_t)s*CC*CC];

    __shared__ float rbuf[4];
    __shared__ float sbuf[4];
    float mx = sum;
    #pragma unroll
    for (int o = 16; o; o >>= 1) mx = fmaxf(mx, __shfl_xor_sync(0xffffffffu, mx, o));
    if ((d & 31) == 0) rbuf[d >> 5] = mx;
    __syncthreads();
    mx = fmaxf(fmaxf(rbuf[0], rbuf[1]), fmaxf(rbuf[2], rbuf[3]));
    float e = expf(sum - mx);
    float tt = e;
    #pragma unroll
    for (int o = 16; o; o >>= 1) tt += __shfl_xor_sync(0xffffffffu, tt, o);
    if ((d & 31) == 0) sbuf[d >> 5] = tt;
    __syncthreads();
    tt = (sbuf[0] + sbuf[1]) + (sbuf[2] + sbuf[3]);
    g_attnT[((size_t)b*CC + d)*CC + c] = e / tt;
}

// ---------------- K4: out = attn @ v --------------------------------------------
__global__ __launch_bounds__(256) void out_kernel(float* __restrict__ out)
{
    __shared__ float vs[CC][64];
    __shared__ float as[8][CC];

    int b  = blockIdx.y;
    int n0 = blockIdx.x * 64;
    int tid = threadIdx.x;
    int tx = tid & 7, ty = tid >> 3;
    int tx8 = tx*8, ty4 = ty*4;

    const float* vb = g_v + (size_t)b*CC*NPT;
    const float* at = g_attnT + (size_t)b*CC*CC;

    #pragma unroll
    for (int it = 0; it < 8; it++) {
        int idx = tid + it*256;
        int r = idx >> 4, v4 = idx & 15;
        int n = n0 + v4*4;
        float4 val = make_float4(0.f, 0.f, 0.f, 0.f);
        if (n < NPT) val = *(const float4*)(vb + (size_t)r*NPT + n);
        *(float4*)&vs[r][v4*4] = val;
    }

    u64 acc[4][4];
    #pragma unroll
    for (int i = 0; i < 4; i++)
        #pragma unroll
        for (int j = 0; j < 4; j++) acc[i][j] = 0ull;

    for (int kc = 0; kc < CC; kc += 8) {
        __syncthreads();
        {
            int k = tid >> 5, c4 = tid & 31;
            *(float4*)&as[k][c4*4] = *(const float4*)(at + (kc+k)*CC + c4*4);
        }
        __syncthreads();
        #pragma unroll
        for (int kk = 0; kk < 8; kk++) {
            float4 av = *(const float4*)&as[kk][ty4];
            u64 a0 = dup2(av.x), a1 = dup2(av.y), a2 = dup2(av.z), a3 = dup2(av.w);
            const float* bb = &vs[kc+kk][tx8];
            ulonglong2 p0 = *(const ulonglong2*)bb;
            ulonglong2 p1 = *(const ulonglong2*)(bb + 4);
            u64 b0 = p0.x, b1 = p0.y, b2 = p1.x, b3 = p1.y;
            FMA_ROW(0, a0, b0, b1, b2, b3)
            FMA_ROW(1, a1, b0, b1, b2, b3)
            FMA_ROW(2, a2, b0, b1, b2, b3)
            FMA_ROW(3, a3, b0, b1, b2, b3)
        }
    }

    int n = n0 + tx8;
    if (n < NPT) {
        #pragma unroll
        for (int i = 0; i < 4; i++) {
            int c = ty4 + i;
            float o[8];
            float2 t;
            t = unpk(acc[i][0]); o[0] = t.x; o[1] = t.y;
            t = unpk(acc[i][1]); o[2] = t.x; o[3] = t.y;
            t = unpk(acc[i][2]); o[4] = t.x; o[5] = t.y;
            t = unpk(acc[i][3]); o[6] = t.x; o[7] = t.y;
            *(float4*)(out + ((size_t)b*CC + c)*NPT + n)     = make_float4(o[0], o[1], o[2], o[3]);
            *(float4*)(out + ((size_t)b*CC + c)*NPT + n + 4) = make_float4(o[4], o[5], o[6], o[7]);
        }
    }
}

// ---------------- host entry ----------------------------------------------------
extern "C" void kernel_launch(void* const* d_in, const int* in_sizes, int n_in,
                              void* d_out, int out_size)
{
    (void)in_sizes; (void)n_in; (void)out_size;
    const float* PC = (const float*)d_in[0];
    const float* X  = (const float*)d_in[1];

    setup_kernel<<<192, 256>>>(
        (const float*)d_in[2],  (const float*)d_in[3],  (const float*)d_in[4],
        (const float*)d_in[5],  (const float*)d_in[6],
        (const float*)d_in[7],  (const float*)d_in[8],  (const float*)d_in[9],
        (const float*)d_in[10], (const float*)d_in[11],
        (const float*)d_in[12], (const float*)d_in[13], (const float*)d_in[14],
        (const float*)d_in[15], (const float*)d_in[16],
        (const float*)d_in[17], (const float*)d_in[18],
        (const float*)d_in[19], (const float*)d_in[20]);

    proj_kernel<<<dim3(NTILES, BATCH), 256>>>(PC, X);
    logits_kernel<<<dim3(SPLIT, 2, BATCH), 256>>>();
    softmax_kernel<<<dim3(CC, BATCH), CC>>>();
    out_kernel<<<dim3(NTILES, BATCH), 256>>>((float*)d_out);
}

// round 4
// speedup vs baseline: 1.5874x; 1.5874x over previous
#include <cuda_runtime.h>
#include <cuda_fp16.h>
#include <cstdint>

#define BATCH 8
#define CC    128
#define NPT   20000
#define NPAD  20480
#define NT_PROJ 160
#define NT_OUT  157
#define SPLIT 32
#define KSPL  640            // NPAD / SPLIT
#define EPSB  1e-5f
#define PITCH 136            // halves per smem tile row (272 B)
#define TILE_BYTES 34816     // 128 * 272

typedef uint32_t u32;

// ---------------- scratch ------------------------------------------------------
__device__ __half g_pcThi[(size_t)BATCH*NPAD*CC];  // [b][n][k]
__device__ __half g_pcTlo[(size_t)BATCH*NPAD*CC];
__device__ __half g_qhi  [(size_t)BATCH*CC*NPAD];  // [b][c][n]
__device__ __half g_qlo  [(size_t)BATCH*CC*NPAD];
__device__ __half g_khi  [(size_t)BATCH*CC*NPAD];  // k + graph_context
__device__ __half g_klo  [(size_t)BATCH*CC*NPAD];
__device__ __half g_vThi [(size_t)BATCH*NPAD*CC];  // [b][n][d]
__device__ __half g_vTlo [(size_t)BATCH*NPAD*CC];
__device__ float  g_part [(size_t)BATCH*SPLIT*CC*CC];
__device__ __half g_ahi  [BATCH*CC*CC];            // attn [b][c][d]
__device__ __half g_alo  [BATCH*CC*CC];
__device__ __half g_whi  [3*CC*CC];                // [p][c][k]
__device__ __half g_wlo  [3*CC*CC];
__device__ float g_shift[3*CC];
__device__ float g_G    [CC*4];
__device__ float g_bsum [CC];

// ---------------- helpers ------------------------------------------------------
__device__ __forceinline__ u32 smem_u32(const void* p) {
    u32 a; asm("{ .reg .u64 t; cvta.to.shared.u64 t, %1; cvt.u32.u64 %0, t; }" : "=r"(a) : "l"(p));
    return a;
}
__device__ __forceinline__ void ldm4(u32* r, u32 addr) {
    asm volatile("ldmatrix.sync.aligned.m8n8.x4.shared.b16 {%0,%1,%2,%3}, [%4];"
        : "=r"(r[0]), "=r"(r[1]), "=r"(r[2]), "=r"(r[3]) : "r"(addr));
}
#define MMA(d, a, b0, b1) \
    asm volatile("mma.sync.aligned.m16n8k16.row.col.f32.f16.f16.f32 " \
        "{%0,%1,%2,%3}, {%4,%5,%6,%7}, {%8,%9}, {%0,%1,%2,%3};" \
        : "+f"((d)[0]), "+f"((d)[1]), "+f"((d)[2]), "+f"((d)[3]) \
        : "r"((a)[0]), "r"((a)[1]), "r"((a)[2]), "r"((a)[3]), "r"(b0), "r"(b1))

__device__ __forceinline__ u32 pack2(__half a, __half b) {
    u32 ua = *(const unsigned short*)&a, ub = *(const unsigned short*)&b;
    return ua | (ub << 16);
}
__device__ __forceinline__ void split_h(float x, __half &hi, __half &lo) {
    hi = __float2half_rn(x);
    lo = __float2half_rn(x - __half2float(hi));
}

// load [128 rows][128 halves] gmem -> smem tile with pitch PITCH
__device__ __forceinline__ void load_tile(__half* dst, const __half* src, size_t pitch_src) {
    for (int idx = threadIdx.x; idx < 2048; idx += 256) {
        int r = idx >> 4, g = idx & 15;
        *(uint4*)(dst + r * PITCH + g * 8) = *(const uint4*)(src + (size_t)r * pitch_src + g * 8);
    }
}

// one K=128 block-GEMM step on [128c x 128n] tile via fp16 hi/lo split (3 MMAs)
// aHt/aLt: smem byte addrs of A tiles (rows = m, k-contig); bHt/bLt: B tiles (rows = n)
__device__ __forceinline__ void gemm_k128(float acc[2][8][4],
                                          u32 aHt, u32 aLt, u32 bHt, u32 bLt,
                                          int wc0, int wn0, int lane)
{
    u32 aoff = (u32)(wc0 + (lane & 15)) * 272 + ((lane >> 4) << 4);
    u32 boff = (u32)(wn0 + ((lane >> 4) << 3) + (lane & 7)) * 272 + (((lane >> 3) & 1) << 4);
    u32 aH[2], aL[2], bH[4], bL[4];
    #pragma unroll
    for (int mt = 0; mt < 2; mt++) { aH[mt] = aHt + aoff + mt*16*272; aL[mt] = aLt + aoff + mt*16*272; }
    #pragma unroll
    for (int ntp = 0; ntp < 4; ntp++) { bH[ntp] = bHt + boff + ntp*16*272; bL[ntp] = bLt + boff + ntp*16*272; }

    #pragma unroll
    for (int ks = 0; ks < 8; ks++) {
        u32 ko = ks * 32;
        u32 AH[2][4], AL[2][4], BH[4][4], BL[4][4];
        #pragma unroll
        for (int mt = 0; mt < 2; mt++) { ldm4(AH[mt], aH[mt] + ko); ldm4(AL[mt], aL[mt] + ko); }
        #pragma unroll
        for (int ntp = 0; ntp < 4; ntp++) { ldm4(BH[ntp], bH[ntp] + ko); ldm4(BL[ntp], bL[ntp] + ko); }
        #pragma unroll
        for (int mt = 0; mt < 2; mt++)
            #pragma unroll
            for (int nt = 0; nt < 8; nt++) {
                int p4 = nt >> 1, o = (nt & 1) * 2;
                MMA(acc[mt][nt], AH[mt], BH[p4][o], BH[p4][o+1]);
                MMA(acc[mt][nt], AH[mt], BL[p4][o], BL[p4][o+1]);
                MMA(acc[mt][nt], AL[mt], BH[p4][o], BH[p4][o+1]);
            }
    }
}

// ---------------- K0: setup ----------------------------------------------------
__global__ void setup_kernel(
    const float* __restrict__ Wq, const float* __restrict__ gq, const float* __restrict__ bq,
    const float* __restrict__ mq, const float* __restrict__ vq,
    const float* __restrict__ Wk, const float* __restrict__ gk, const float* __restrict__ bk,
    const float* __restrict__ mk, const float* __restrict__ vk,
    const float* __restrict__ Wv, const float* __restrict__ gv, const float* __restrict__ bv,
    const float* __restrict__ mv, const float* __restrict__ vv,
    const float* __restrict__ Wg1, const float* __restrict__ bg1,
    const float* __restrict__ Wg2, const float* __restrict__ bg2)
{
    int idx = blockIdx.x * 256 + threadIdx.x;
    const float invtemp = rsqrtf(128.0f);
    if (idx < 3*CC*CC) {
        int p = idx / (CC*CC);
        int r = idx - p*(CC*CC);
        int c = r >> 7, k = r & 127;
        const float* W  = (p==0 ? Wq : (p==1 ? Wk : Wv));
        const float* g  = (p==0 ? gq : (p==1 ? gk : gv));
        const float* vr = (p==0 ? vq : (p==1 ? vk : vv));
        float scale = g[c] * rsqrtf(vr[c] + EPSB);
        if (p == 0) scale *= invtemp;
        float w = W[c*CC + k] * scale;
        __half hi, lo; split_h(w, hi, lo);
        g_whi[idx] = hi; g_wlo[idx] = lo;
    }
    if (idx < 3*CC) {
        int p = idx >> 7, c = idx & 127;
        const float* g  = (p==0 ? gq : (p==1 ? gk : gv));
        const float* vr = (p==0 ? vq : (p==1 ? vk : vv));
        const float* bb = (p==0 ? bq : (p==1 ? bk : bv));
        const float* mm = (p==0 ? mq : (p==1 ? mk : mv));
        float scale = g[c] * rsqrtf(vr[c] + EPSB);
        float sh = bb[c] - mm[c]*scale;
        if (p == 0) sh *= invtemp;
        g_shift[idx] = sh;
    }
    if (idx < CC) {
        g_G[idx*4+0] = Wg1[idx*2+0];
        g_G[idx*4+1] = Wg1[idx*2+1];
        g_G[idx*4+2] = Wg2[idx*2+0];
        g_G[idx*4+3] = Wg2[idx*2+1];
        g_bsum[idx]  = bg1[idx] + bg2[idx];
    }
}

// ---------------- K1: transpose pc -> pcT hi/lo fp16 ---------------------------
__global__ __launch_bounds__(256) void transpose_kernel(const float* __restrict__ pc)
{
    __shared__ float t[128][65];
    int b = blockIdx.y, n0 = blockIdx.x * 128;
    int tid = threadIdx.x;
    for (int half_i = 0; half_i < 2; half_i++) {
        int nb = n0 + half_i * 64;
        __syncthreads();
        for (int idx = tid; idx < 2048; idx += 256) {
            int k = idx >> 4, nv = idx & 15;
            int n = nb + nv*4;
            float4 v = make_float4(0.f, 0.f, 0.f, 0.f);
            if (n < NPT) v = *(const float4*)(pc + ((size_t)b*CC + k)*NPT + n);
            t[k][nv*4+0] = v.x; t[k][nv*4+1] = v.y; t[k][nv*4+2] = v.z; t[k][nv*4+3] = v.w;
        }
        __syncthreads();
        for (int idx = tid; idx < 1024; idx += 256) {
            int n = idx >> 4, kg = idx & 15;
            u32 hp[4], lp[4];
            #pragma unroll
            for (int j = 0; j < 4; j++) {
                __half h0, l0, h1, l1;
                split_h(t[kg*8 + j*2    ][n], h0, l0);
                split_h(t[kg*8 + j*2 + 1][n], h1, l1);
                hp[j] = pack2(h0, h1); lp[j] = pack2(l0, l1);
            }
            size_t row = (size_t)b*NPAD + nb + n;
            *(uint4*)(g_pcThi + row*CC + kg*8) = *(uint4*)hp;
            *(uint4*)(g_pcTlo + row*CC + kg*8) = *(uint4*)lp;
        }
    }
}

// ---------------- K2: proj (q, k+gc, v) ----------------------------------------
// smem byte offsets
#define PT_H 0
#define PT_L 34816
#define W_H  69632
#define W_L  104448
#define VSTG_H 69632          // reuse W region for v staging (p==2 only)
#define VSTG_L 102912
#define XS 139264
#define SH 141312
#define GG 142848
#define BS 144896
#define PROJ_SMEM 145408

__global__ __launch_bounds__(256, 1) void proj_kernel(const float* __restrict__ x_all)
{
    extern __shared__ char smem[];
    u32 sb = smem_u32(smem);
    int tid = threadIdx.x, wid = tid >> 5, lane = tid & 31;
    int b = blockIdx.y, n0 = blockIdx.x * 128;
    int wc0 = (wid & 3) * 32, wn0 = (wid >> 2) * 64;
    int lrow = lane >> 2, lcol = (lane & 3) * 2;

    // consts
    for (int i = tid; i < 4*128; i += 256) {
        int ch = i >> 7, n = i & 127, gn = n0 + n;
        ((float*)(smem + XS))[i] = (gn < NPT) ? x_all[((size_t)b*4 + ch)*NPT + gn] : 0.f;
    }
    for (int i = tid; i < 384; i += 256) ((float*)(smem + SH))[i] = g_shift[i];
    if (tid < 128) {
        *(float4*)((float*)(smem + GG) + tid*4) = *(const float4*)&g_G[tid*4];
        ((float*)(smem + BS))[tid] = g_bsum[tid];
    }
    // B tiles (pcT) resident for all three projections
    load_tile((__half*)(smem + PT_H), g_pcThi + ((size_t)b*NPAD + n0)*CC, CC);
    load_tile((__half*)(smem + PT_L), g_pcTlo + ((size_t)b*NPAD + n0)*CC, CC);

    for (int p = 0; p < 3; p++) {
        __syncthreads();
        load_tile((__half*)(smem + W_H), g_whi + (size_t)p*CC*CC, CC);
        load_tile((__half*)(smem + W_L), g_wlo + (size_t)p*CC*CC, CC);
        __syncthreads();

        float acc[2][8][4];
        #pragma unroll
        for (int i = 0; i < 2; i++)
            #pragma unroll
            for (int j = 0; j < 8; j++)
                #pragma unroll
                for (int q = 0; q < 4; q++) acc[i][j][q] = 0.f;

        gemm_k128(acc, sb + W_H, sb + W_L, sb + PT_H, sb + PT_L, wc0, wn0, lane);
        __syncthreads();   // all warps done reading W region before staging/next load

        const float* xs = (const float*)(smem + XS);
        if (p < 2) {
            __half* dh = (p == 0 ? g_qhi : g_khi) + (size_t)b*CC*NPAD + n0;
            __half* dl = (p == 0 ? g_qlo : g_klo) + (size_t)b*CC*NPAD + n0;
            #pragma unroll
            for (int mt = 0; mt < 2; mt++)
                #pragma unroll
                for (int hr = 0; hr < 2; hr++) {
                    int c = wc0 + mt*16 + hr*8 + lrow;
                    float sh = ((float*)(smem + SH))[p*128 + c];
                    float gg0 = 0.f, gg1 = 0.f, gg2 = 0.f, gg3 = 0.f, bsv = 0.f;
                    if (p == 1) {
                        gg0 = ((float*)(smem + GG))[c*4+0];
                        gg1 = ((float*)(smem + GG))[c*4+1];
                        gg2 = ((float*)(smem + GG))[c*4+2];
                        gg3 = ((float*)(smem + GG))[c*4+3];
                        bsv = ((float*)(smem + BS))[c];
                    }
                    #pragma unroll
                    for (int nt = 0; nt < 8; nt++) {
                        int nl = wn0 + nt*8 + lcol;
                        float y0 = fmaxf(acc[mt][nt][hr*2+0] + sh, 0.f);
                        float y1 = fmaxf(acc[mt][nt][hr*2+1] + sh, 0.f);
                        if (p == 1) {
                            y0 += gg0*xs[nl]   + gg1*xs[128+nl]   + gg2*xs[256+nl]   + gg3*xs[384+nl]   + bsv;
                            y1 += gg0*xs[nl+1] + gg1*xs[128+nl+1] + gg2*xs[256+nl+1] + gg3*xs[384+nl+1] + bsv;
                        }
                        if (n0 + nl     >= NPT) y0 = 0.f;
                        if (n0 + nl + 1 >= NPT) y1 = 0.f;
                        __half h0, l0, h1, l1;
                        split_h(y0, h0, l0); split_h(y1, h1, l1);
                        *(u32*)(dh + (size_t)c*NPAD + nl) = pack2(h0, h1);
                        *(u32*)(dl + (size_t)c*NPAD + nl) = pack2(l0, l1);
                    }
                }
        } else {
            // v: stage transposed [n][d] in reused W region, then coalesced copy
            #pragma unroll
            for (int mt = 0; mt < 2; mt++)
                #pragma unroll
                for (int hr = 0; hr < 2; hr++) {
                    int c = wc0 + mt*16 + hr*8 + lrow;
                    float sh = ((float*)(smem + SH))[2*128 + c];
                    #pragma unroll
                    for (int nt = 0; nt < 8; nt++) {
                        int nl = wn0 + nt*8 + lcol;
                        float y0 = fmaxf(acc[mt][nt][hr*2+0] + sh, 0.f);
                        float y1 = fmaxf(acc[mt][nt][hr*2+1] + sh, 0.f);
                        if (n0 + nl     >= NPT) y0 = 0.f;
                        if (n0 + nl + 1 >= NPT) y1 = 0.f;
                        __half h0, l0, h1, l1;
                        split_h(y0, h0, l0); split_h(y1, h1, l1);
                        *(__half*)(smem + VSTG_H + (nl  )*260 + c*2) = h0;
                        *(__half*)(smem + VSTG_H + (nl+1)*260 + c*2) = h1;
                        *(__half*)(smem + VSTG_L + (nl  )*260 + c*2) = l0;
                        *(__half*)(smem + VSTG_L + (nl+1)*260 + c*2) = l1;
                    }
                }
            __syncthreads();
            __half* dh = g_vThi + ((size_t)b*NPAD + n0)*CC;
            __half* dl = g_vTlo + ((size_t)b*NPAD + n0)*CC;
            for (int idx = tid; idx < 8192; idx += 256) {
                int n = idx >> 6, col = idx & 63;
                ((u32*)(dh + (size_t)n*CC))[col] = *(u32*)(smem + VSTG_H + n*260 + col*4);
                ((u32*)(dl + (size_t)n*CC))[col] = *(u32*)(smem + VSTG_L + n*260 + col*4);
            }
        }
    }
}

// ---------------- K3: logits partials ------------------------------------------
#define LQ_H 0
#define LQ_L 34816
#define LK_H 69632
#define LK_L 104448
#define LOG_SMEM 139264

__global__ __launch_bounds__(256, 1) void logits_kernel()
{
    extern __shared__ char smem[];
    u32 sb = smem_u32(smem);
    int tid = threadIdx.x, wid = tid >> 5, lane = tid & 31;
    int s = blockIdx.x, b = blockIdx.y;
    int k0 = s * KSPL;
    int wc0 = (wid & 3) * 32, wn0 = (wid >> 2) * 64;
    int lrow = lane >> 2, lcol = (lane & 3) * 2;

    float acc[2][8][4];
    #pragma unroll
    for (int i = 0; i < 2; i++)
        #pragma unroll
        for (int j = 0; j < 8; j++)
            #pragma unroll
            for (int q = 0; q < 4; q++) acc[i][j][q] = 0.f;

    const __half* qh = g_qhi + (size_t)b*CC*NPAD + k0;
    const __half* ql = g_qlo + (size_t)b*CC*NPAD + k0;
    const __half* kh = g_khi + (size_t)b*CC*NPAD + k0;
    const __half* kl = g_klo + (size_t)b*CC*NPAD + k0;

    for (int ch = 0; ch < KSPL/128; ch++) {
        __syncthreads();
        load_tile((__half*)(smem + LQ_H), qh + ch*128, NPAD);
        load_tile((__half*)(smem + LQ_L), ql + ch*128, NPAD);
        load_tile((__half*)(smem + LK_H), kh + ch*128, NPAD);
        load_tile((__half*)(smem + LK_L), kl + ch*128, NPAD);
        __syncthreads();
        gemm_k128(acc, sb + LQ_H, sb + LQ_L, sb + LK_H, sb + LK_L, wc0, wn0, lane);
    }

    float* dst = g_part + ((size_t)(b*SPLIT + s))*CC*CC;
    #pragma unroll
    for (int mt = 0; mt < 2; mt++)
        #pragma unroll
        for (int hr = 0; hr < 2; hr++) {
            int c = wc0 + mt*16 + hr*8 + lrow;
            #pragma unroll
            for (int nt = 0; nt < 8; nt++) {
                int d = wn0 + nt*8 + lcol;
                *(float2*)(dst + (size_t)c*CC + d) =
                    make_float2(acc[mt][nt][hr*2+0], acc[mt][nt][hr*2+1]);
            }
        }
}

// ---------------- K4: reduce + softmax -> attn hi/lo ---------------------------
__global__ void softmax_kernel()
{
    int c = blockIdx.x, b = blockIdx.y;
    int d = threadIdx.x;
    const float* p = g_part + ((size_t)b*SPLIT*CC + c)*CC + d;
    float sum = 0.f;
    #pragma unroll
    for (int s = 0; s < SPLIT; s++) sum += p[(size_t)s*CC*CC];

    __shared__ float rbuf[4], sbuf[4];
    float mx = sum;
    #pragma unroll
    for (int o = 16; o; o >>= 1) mx = fmaxf(mx, __shfl_xor_sync(0xffffffffu, mx, o));
    if ((d & 31) == 0) rbuf[d >> 5] = mx;
    __syncthreads();
    mx = fmaxf(fmaxf(rbuf[0], rbuf[1]), fmaxf(rbuf[2], rbuf[3]));
    float e = expf(sum - mx);
    float tt = e;
    #pragma unroll
    for (int o = 16; o; o >>= 1) tt += __shfl_xor_sync(0xffffffffu, tt, o);
    if ((d & 31) == 0) sbuf[d >> 5] = tt;
    __syncthreads();
    tt = (sbuf[0] + sbuf[1]) + (sbuf[2] + sbuf[3]);
    float w = e / tt;
    __half h, l; split_h(w, h, l);
    size_t o = ((size_t)b*CC + c)*CC + d;
    g_ahi[o] = h; g_alo[o] = l;
}

// ---------------- K5: out = attn @ v -------------------------------------------
#define OA_H 0
#define OA_L 34816
#define OV_H 69632
#define OV_L 104448
#define OUT_SMEM 139264

__global__ __launch_bounds__(256, 1) void out_kernel(float* __restrict__ out)
{
    extern __shared__ char smem[];
    u32 sb = smem_u32(smem);
    int tid = threadIdx.x, wid = tid >> 5, lane = tid & 31;
    int b = blockIdx.y, n0 = blockIdx.x * 128;
    int wc0 = (wid & 3) * 32, wn0 = (wid >> 2) * 64;
    int lrow = lane >> 2, lcol = (lane & 3) * 2;

    load_tile((__half*)(smem + OA_H), g_ahi + (size_t)b*CC*CC, CC);
    load_tile((__half*)(smem + OA_L), g_alo + (size_t)b*CC*CC, CC);
    load_tile((__half*)(smem + OV_H), g_vThi + ((size_t)b*NPAD + n0)*CC, CC);
    load_tile((__half*)(smem + OV_L), g_vTlo + ((size_t)b*NPAD + n0)*CC, CC);
    __syncthreads();

    float acc[2][8][4];
    #pragma unroll
    for (int i = 0; i < 2; i++)
        #pragma unroll
        for (int j = 0; j < 8; j++)
            #pragma unroll
            for (int q = 0; q < 4; q++) acc[i][j][q] = 0.f;

    gemm_k128(acc, sb + OA_H, sb + OA_L, sb + OV_H, sb + OV_L, wc0, wn0, lane);

    #pragma unroll
    for (int mt = 0; mt < 2; mt++)
        #pragma unroll
        for (int hr = 0; hr < 2; hr++) {
            int c = wc0 + mt*16 + hr*8 + lrow;
            #pragma unroll
            for (int nt = 0; nt < 8; nt++) {
                int n = n0 + wn0 + nt*8 + lcol;
                if (n < NPT)   // NPT even, pairs never straddle
                    *(float2*)(out + ((size_t)b*CC + c)*NPT + n) =
                        make_float2(acc[mt][nt][hr*2+0], acc[mt][nt][hr*2+1]);
            }
        }
}

// ---------------- host entry ----------------------------------------------------
extern "C" void kernel_launch(void* const* d_in, const int* in_sizes, int n_in,
                              void* d_out, int out_size)
{
    (void)in_sizes; (void)n_in; (void)out_size;
    const float* PC = (const float*)d_in[0];
    const float* X  = (const float*)d_in[1];

    cudaFuncSetAttribute(proj_kernel,   cudaFuncAttributeMaxDynamicSharedMemorySize, PROJ_SMEM);
    cudaFuncSetAttribute(logits_kernel, cudaFuncAttributeMaxDynamicSharedMemorySize, LOG_SMEM);
    cudaFuncSetAttribute(out_kernel,    cudaFuncAttributeMaxDynamicSharedMemorySize, OUT_SMEM);

    setup_kernel<<<192, 256>>>(
        (const float*)d_in[2],  (const float*)d_in[3],  (const float*)d_in[4],
        (const float*)d_in[5],  (const float*)d_in[6],
        (const float*)d_in[7],  (const float*)d_in[8],  (const float*)d_in[9],
        (const float*)d_in[10], (const float*)d_in[11],
        (const float*)d_in[12], (const float*)d_in[13], (const float*)d_in[14],
        (const float*)d_in[15], (const float*)d_in[16],
        (const float*)d_in[17], (const float*)d_in[18],
        (const float*)d_in[19], (const float*)d_in[20]);

    transpose_kernel<<<dim3(NT_PROJ, BATCH), 256>>>(PC);
    proj_kernel<<<dim3(NT_PROJ, BATCH), 256, PROJ_SMEM>>>(X);
    logits_kernel<<<dim3(SPLIT, BATCH), 256, LOG_SMEM>>>();
    softmax_kernel<<<dim3(CC, BATCH), CC>>>();
    out_kernel<<<dim3(NT_OUT, BATCH), 256, OUT_SMEM>>>((float*)d_out);
}

// round 5
// speedup vs baseline: 2.8108x; 1.7707x over previous
#include <cuda_runtime.h>
#include <cuda_fp16.h>
#include <cstdint>

#define BATCH 8
#define CC    128
#define NPT   20000
#define NPAD  20480
#define NT_PROJ 160
#define NT_OUT  157
#define SPLIT 16
#define KSPL  1280           // NPAD / SPLIT
#define EPSB  1e-5f

typedef uint32_t u32;

// ---------------- scratch ------------------------------------------------------
__device__ __half g_pcThi[(size_t)BATCH*NPAD*CC];  // [b][n][k]
__device__ __half g_pcTlo[(size_t)BATCH*NPAD*CC];
__device__ __half g_qhi  [(size_t)BATCH*CC*NPAD];  // [b][c][n]
__device__ __half g_qlo  [(size_t)BATCH*CC*NPAD];
__device__ __half g_khi  [(size_t)BATCH*CC*NPAD];  // k + graph_context
__device__ __half g_klo  [(size_t)BATCH*CC*NPAD];
__device__ __half g_vThi [(size_t)BATCH*NPAD*CC];  // [b][n][d]
__device__ float  g_part [(size_t)BATCH*SPLIT*CC*CC];
__device__ __half g_ahi  [BATCH*CC*CC];            // attn [b][c][d]
__device__ __half g_whi  [3*CC*CC];                // [p][c][k]
__device__ __half g_wlo  [3*CC*CC];
__device__ float g_shift[3*CC];
__device__ float g_G    [CC*4];
__device__ float g_bsum [CC];

// ---------------- helpers ------------------------------------------------------
__device__ __forceinline__ u32 smem_u32(const void* p) {
    u32 a; asm("{ .reg .u64 t; cvta.to.shared.u64 t, %1; cvt.u32.u64 %0, t; }" : "=r"(a) : "l"(p));
    return a;
}
__device__ __forceinline__ void ldm4(u32* r, u32 addr) {
    asm volatile("ldmatrix.sync.aligned.m8n8.x4.shared.b16 {%0,%1,%2,%3}, [%4];"
        : "=r"(r[0]), "=r"(r[1]), "=r"(r[2]), "=r"(r[3]) : "r"(addr));
}
#define MMA(d, a, b0, b1) \
    asm volatile("mma.sync.aligned.m16n8k16.row.col.f32.f16.f16.f32 " \
        "{%0,%1,%2,%3}, {%4,%5,%6,%7}, {%8,%9}, {%0,%1,%2,%3};" \
        : "+f"((d)[0]), "+f"((d)[1]), "+f"((d)[2]), "+f"((d)[3]) \
        : "r"((a)[0]), "r"((a)[1]), "r"((a)[2]), "r"((a)[3]), "r"(b0), "r"(b1))

__device__ __forceinline__ void cpa16(u32 dst, const void* src) {
    asm volatile("cp.async.cg.shared.global [%0], [%1], 16;" :: "r"(dst), "l"(src));
}
#define CP_COMMIT() asm volatile("cp.async.commit_group;" ::: "memory")
#define CP_WAIT(n)  asm volatile("cp.async.wait_group %0;" :: "n"(n) : "memory")

__device__ __forceinline__ u32 pack2(__half a, __half b) {
    u32 ua = *(const unsigned short*)&a, ub = *(const unsigned short*)&b;
    return ua | (ub << 16);
}
__device__ __forceinline__ void split_h(float x, __half &hi, __half &lo) {
    hi = __float2half_rn(x);
    lo = __float2half_rn(x - __half2float(hi));
}

// cp.async [128 rows][64 halves] -> pitch 144B tile
__device__ __forceinline__ void cpa_tile64(u32 dst, const __half* src, size_t pitch) {
    for (int idx = threadIdx.x; idx < 1024; idx += 256) {
        int r = idx >> 3, g = idx & 7;
        cpa16(dst + r*144 + g*16, src + (size_t)r*pitch + g*8);
    }
}
// cp.async [128 rows][128 halves] -> pitch 272B tile
__device__ __forceinline__ void cpa_tile128(u32 dst, const __half* src, size_t pitch) {
    for (int idx = threadIdx.x; idx < 2048; idx += 256) {
        int r = idx >> 4, g = idx & 15;
        cpa16(dst + r*272 + g*16, src + (size_t)r*pitch + g*8);
    }
}

// K=128 tile (pitch 272B), fp16 hi/lo split (3 MMAs)
__device__ __forceinline__ void gemm_k128(float acc[2][8][4],
                                          u32 aHt, u32 aLt, u32 bHt, u32 bLt,
                                          int wc0, int wn0, int lane)
{
    u32 aoff = (u32)(wc0 + (lane & 15)) * 272 + ((lane >> 4) << 4);
    u32 boff = (u32)(wn0 + ((lane >> 4) << 3) + (lane & 7)) * 272 + (((lane >> 3) & 1) << 4);
    #pragma unroll
    for (int ks = 0; ks < 8; ks++) {
        u32 ko = ks * 32;
        u32 AH[2][4], AL[2][4], BH[4][4], BL[4][4];
        #pragma unroll
        for (int mt = 0; mt < 2; mt++) {
            ldm4(AH[mt], aHt + aoff + mt*16*272 + ko);
            ldm4(AL[mt], aLt + aoff + mt*16*272 + ko);
        }
        #pragma unroll
        for (int ntp = 0; ntp < 4; ntp++) {
            ldm4(BH[ntp], bHt + boff + ntp*16*272 + ko);
            ldm4(BL[ntp], bLt + boff + ntp*16*272 + ko);
        }
        #pragma unroll
        for (int mt = 0; mt < 2; mt++)
            #pragma unroll
            for (int nt = 0; nt < 8; nt++) {
                int p4 = nt >> 1, o = (nt & 1) * 2;
                MMA(acc[mt][nt], AH[mt], BH[p4][o], BH[p4][o+1]);
                MMA(acc[mt][nt], AH[mt], BL[p4][o], BL[p4][o+1]);
                MMA(acc[mt][nt], AL[mt], BH[p4][o], BH[p4][o+1]);
            }
    }
}

// K=64 chunk (pitch 144B), split (3 MMAs)
__device__ __forceinline__ void gemm64_split(float acc[2][8][4],
                                             u32 aH, u32 aL, u32 bH, u32 bL,
                                             u32 aoff, u32 boff)
{
    #pragma unroll
    for (int ks = 0; ks < 4; ks++) {
        u32 ko = ks * 32;
        u32 AH[2][4], AL[2][4], BH[4][4], BL[4][4];
        #pragma unroll
        for (int mt = 0; mt < 2; mt++) {
            ldm4(AH[mt], aH + aoff + mt*16*144 + ko);
            ldm4(AL[mt], aL + aoff + mt*16*144 + ko);
        }
        #pragma unroll
        for (int ntp = 0; ntp < 4; ntp++) {
            ldm4(BH[ntp], bH + boff + ntp*16*144 + ko);
            ldm4(BL[ntp], bL + boff + ntp*16*144 + ko);
        }
        #pragma unroll
        for (int mt = 0; mt < 2; mt++)
            #pragma unroll
            for (int nt = 0; nt < 8; nt++) {
                int p4 = nt >> 1, o = (nt & 1) * 2;
                MMA(acc[mt][nt], AH[mt], BH[p4][o], BH[p4][o+1]);
                MMA(acc[mt][nt], AH[mt], BL[p4][o], BL[p4][o+1]);
                MMA(acc[mt][nt], AL[mt], BH[p4][o], BH[p4][o+1]);
            }
    }
}

// K=64 chunk (pitch 144B), hi-only (1 MMA)
__device__ __forceinline__ void gemm64_one(float acc[2][8][4],
                                           u32 aT, u32 bT, u32 aoff, u32 boff)
{
    #pragma unroll
    for (int ks = 0; ks < 4; ks++) {
        u32 ko = ks * 32;
        u32 A[2][4], B[4][4];
        #pragma unroll
        for (int mt = 0; mt < 2; mt++) ldm4(A[mt], aT + aoff + mt*16*144 + ko);
        #pragma unroll
        for (int ntp = 0; ntp < 4; ntp++) ldm4(B[ntp], bT + boff + ntp*16*144 + ko);
        #pragma unroll
        for (int mt = 0; mt < 2; mt++)
            #pragma unroll
            for (int nt = 0; nt < 8; nt++) {
                int p4 = nt >> 1, o = (nt & 1) * 2;
                MMA(acc[mt][nt], A[mt], B[p4][o], B[p4][o+1]);
            }
    }
}

// ---------------- K0: setup ----------------------------------------------------
__global__ void setup_kernel(
    const float* __restrict__ Wq, const float* __restrict__ gq, const float* __restrict__ bq,
    const float* __restrict__ mq, const float* __restrict__ vq,
    const float* __restrict__ Wk, const float* __restrict__ gk, const float* __restrict__ bk,
    const float* __restrict__ mk, const float* __restrict__ vk,
    const float* __restrict__ Wv, const float* __restrict__ gv, const float* __restrict__ bv,
    const float* __restrict__ mv, const float* __restrict__ vv,
    const float* __restrict__ Wg1, const float* __restrict__ bg1,
    const float* __restrict__ Wg2, const float* __restrict__ bg2)
{
    int idx = blockIdx.x * 256 + threadIdx.x;
    const float invtemp = rsqrtf(128.0f);
    if (idx < 3*CC*CC) {
        int p = idx / (CC*CC);
        int r = idx - p*(CC*CC);
        int c = r >> 7, k = r & 127;
        const float* W  = (p==0 ? Wq : (p==1 ? Wk : Wv));
        const float* g  = (p==0 ? gq : (p==1 ? gk : gv));
        const float* vr = (p==0 ? vq : (p==1 ? vk : vv));
        float scale = g[c] * rsqrtf(vr[c] + EPSB);
        if (p == 0) scale *= invtemp;
        float w = W[c*CC + k] * scale;
        __half hi, lo; split_h(w, hi, lo);
        g_whi[idx] = hi; g_wlo[idx] = lo;
    }
    if (idx < 3*CC) {
        int p = idx >> 7, c = idx & 127;
        const float* g  = (p==0 ? gq : (p==1 ? gk : gv));
        const float* vr = (p==0 ? vq : (p==1 ? vk : vv));
        const float* bb = (p==0 ? bq : (p==1 ? bk : bv));
        const float* mm = (p==0 ? mq : (p==1 ? mk : mv));
        float scale = g[c] * rsqrtf(vr[c] + EPSB);
        float sh = bb[c] - mm[c]*scale;
        if (p == 0) sh *= invtemp;
        g_shift[idx] = sh;
    }
    if (idx < CC) {
        g_G[idx*4+0] = Wg1[idx*2+0];
        g_G[idx*4+1] = Wg1[idx*2+1];
        g_G[idx*4+2] = Wg2[idx*2+0];
        g_G[idx*4+3] = Wg2[idx*2+1];
        g_bsum[idx]  = bg1[idx] + bg2[idx];
    }
}

// ---------------- K1: transpose pc -> pcT hi/lo fp16 ---------------------------
__global__ __launch_bounds__(256) void transpose_kernel(const float* __restrict__ pc)
{
    __shared__ float t[128][65];
    int b = blockIdx.y, n0 = blockIdx.x * 128;
    int tid = threadIdx.x;
    for (int half_i = 0; half_i < 2; half_i++) {
        int nb = n0 + half_i * 64;
        __syncthreads();
        for (int idx = tid; idx < 2048; idx += 256) {
            int k = idx >> 4, nv = idx & 15;
            int n = nb + nv*4;
            float4 v = make_float4(0.f, 0.f, 0.f, 0.f);
            if (n < NPT) v = *(const float4*)(pc + ((size_t)b*CC + k)*NPT + n);
            t[k][nv*4+0] = v.x; t[k][nv*4+1] = v.y; t[k][nv*4+2] = v.z; t[k][nv*4+3] = v.w;
        }
        __syncthreads();
        for (int idx = tid; idx < 1024; idx += 256) {
            int n = idx >> 4, kg = idx & 15;
            u32 hp[4], lp[4];
            #pragma unroll
            for (int j = 0; j < 4; j++) {
                __half h0, l0, h1, l1;
                split_h(t[kg*8 + j*2    ][n], h0, l0);
                split_h(t[kg*8 + j*2 + 1][n], h1, l1);
                hp[j] = pack2(h0, h1); lp[j] = pack2(l0, l1);
            }
            size_t row = (size_t)b*NPAD + nb + n;
            *(uint4*)(g_pcThi + row*CC + kg*8) = *(uint4*)hp;
            *(uint4*)(g_pcTlo + row*CC + kg*8) = *(uint4*)lp;
        }
    }
}

// ---------------- K2: proj (q, k+gc, v) with double-buffered W -----------------
#define PT_H 0
#define PT_L 34816
#define WB0  69632            // wh, wl at +34816; buf stride 69632
#define VSTG_H 139264         // = WB1 region, reused for v hi staging (p==2)
#define XS 208896
#define SH 210944
#define GG 212480
#define BS 214528
#define PROJ_SMEM 215040

__global__ __launch_bounds__(256, 1) void proj_kernel(const float* __restrict__ x_all)
{
    extern __shared__ char smem[];
    u32 sb = smem_u32(smem);
    int tid = threadIdx.x, wid = tid >> 5, lane = tid & 31;
    int b = blockIdx.y, n0 = blockIdx.x * 128;
    int wc0 = (wid & 3) * 32, wn0 = (wid >> 2) * 64;
    int lrow = lane >> 2, lcol = (lane & 3) * 2;

    // group 0: pcT tiles ; group 1: W(0)
    cpa_tile128(sb + PT_H, g_pcThi + ((size_t)b*NPAD + n0)*CC, CC);
    cpa_tile128(sb + PT_L, g_pcTlo + ((size_t)b*NPAD + n0)*CC, CC);
    CP_COMMIT();
    cpa_tile128(sb + WB0,          g_whi, CC);
    cpa_tile128(sb + WB0 + 34816,  g_wlo, CC);
    CP_COMMIT();

    // consts
    for (int i = tid; i < 4*128; i += 256) {
        int ch = i >> 7, n = i & 127, gn = n0 + n;
        ((float*)(smem + XS))[i] = (gn < NPT) ? x_all[((size_t)b*4 + ch)*NPT + gn] : 0.f;
    }
    for (int i = tid; i < 384; i += 256) ((float*)(smem + SH))[i] = g_shift[i];
    if (tid < 128) {
        *(float4*)((float*)(smem + GG) + tid*4) = *(const float4*)&g_G[tid*4];
        ((float*)(smem + BS))[tid] = g_bsum[tid];
    }

    for (int p = 0; p < 3; p++) {
        if (p + 1 < 3) {
            u32 wb = sb + WB0 + ((p + 1) & 1) * 69632;
            cpa_tile128(wb,         g_whi + (size_t)(p+1)*CC*CC, CC);
            cpa_tile128(wb + 34816, g_wlo + (size_t)(p+1)*CC*CC, CC);
            CP_COMMIT();
        }
        if (p < 2) { CP_WAIT(1); } else { CP_WAIT(0); }
        __syncthreads();

        float acc[2][8][4];
        #pragma unroll
        for (int i = 0; i < 2; i++)
            #pragma unroll
            for (int j = 0; j < 8; j++)
                #pragma unroll
                for (int q = 0; q < 4; q++) acc[i][j][q] = 0.f;

        u32 wb = sb + WB0 + (p & 1) * 69632;
        gemm_k128(acc, wb, wb + 34816, sb + PT_H, sb + PT_L, wc0, wn0, lane);

        const float* xs = (const float*)(smem + XS);
        if (p < 2) {
            __half* dh = (p == 0 ? g_qhi : g_khi) + (size_t)b*CC*NPAD + n0;
            __half* dl = (p == 0 ? g_qlo : g_klo) + (size_t)b*CC*NPAD + n0;
            #pragma unroll
            for (int mt = 0; mt < 2; mt++)
                #pragma unroll
                for (int hr = 0; hr < 2; hr++) {
                    int c = wc0 + mt*16 + hr*8 + lrow;
                    float sh = ((float*)(smem + SH))[p*128 + c];
                    float gg0 = 0.f, gg1 = 0.f, gg2 = 0.f, gg3 = 0.f, bsv = 0.f;
                    if (p == 1) {
                        gg0 = ((float*)(smem + GG))[c*4+0];
                        gg1 = ((float*)(smem + GG))[c*4+1];
                        gg2 = ((float*)(smem + GG))[c*4+2];
                        gg3 = ((float*)(smem + GG))[c*4+3];
                        bsv = ((float*)(smem + BS))[c];
                    }
                    #pragma unroll
                    for (int nt = 0; nt < 8; nt++) {
                        int nl = wn0 + nt*8 + lcol;
                        float y0 = fmaxf(acc[mt][nt][hr*2+0] + sh, 0.f);
                        float y1 = fmaxf(acc[mt][nt][hr*2+1] + sh, 0.f);
                        if (p == 1) {
                            y0 += gg0*xs[nl]   + gg1*xs[128+nl]   + gg2*xs[256+nl]   + gg3*xs[384+nl]   + bsv;
                            y1 += gg0*xs[nl+1] + gg1*xs[128+nl+1] + gg2*xs[256+nl+1] + gg3*xs[384+nl+1] + bsv;
                        }
                        if (n0 + nl     >= NPT) y0 = 0.f;
                        if (n0 + nl + 1 >= NPT) y1 = 0.f;
                        __half h0, l0, h1, l1;
                        split_h(y0, h0, l0); split_h(y1, h1, l1);
                        *(u32*)(dh + (size_t)c*NPAD + nl) = pack2(h0, h1);
                        *(u32*)(dl + (size_t)c*NPAD + nl) = pack2(l0, l1);
                    }
                }
            __syncthreads();   // done reading W buf before its next prefetch overwrite
        } else {
            // v: hi only, staged transposed [n][d] in the dead W buffer 1
            #pragma unroll
            for (int mt = 0; mt < 2; mt++)
                #pragma unroll
                for (int hr = 0; hr < 2; hr++) {
                    int c = wc0 + mt*16 + hr*8 + lrow;
                    float sh = ((float*)(smem + SH))[2*128 + c];
                    #pragma unroll
                    for (int nt = 0; nt < 8; nt++) {
                        int nl = wn0 + nt*8 + lcol;
                        float y0 = fmaxf(acc[mt][nt][hr*2+0] + sh, 0.f);
                        float y1 = fmaxf(acc[mt][nt][hr*2+1] + sh, 0.f);
                        if (n0 + nl     >= NPT) y0 = 0.f;
                        if (n0 + nl + 1 >= NPT) y1 = 0.f;
                        *(__half*)(smem + VSTG_H + (nl  )*260 + c*2) = __float2half_rn(y0);
                        *(__half*)(smem + VSTG_H + (nl+1)*260 + c*2) = __float2half_rn(y1);
                    }
                }
            __syncthreads();
            __half* dh = g_vThi + ((size_t)b*NPAD + n0)*CC;
            for (int idx = tid; idx < 8192; idx += 256) {
                int n = idx >> 6, col = idx & 63;
                ((u32*)(dh + (size_t)n*CC))[col] = *(u32*)(smem + VSTG_H + n*260 + col*4);
            }
        }
    }
}

// ---------------- K3: logits partials (3-stage cp.async pipeline) --------------
#define LTILE  18432
#define LSTAGE 73728
#define LNCH   20            // KSPL / 64
#define LOG_SMEM 221184

__global__ __launch_bounds__(256, 1) void logits_kernel()
{
    extern __shared__ char smem[];
    u32 sb = smem_u32(smem);
    int tid = threadIdx.x, wid = tid >> 5, lane = tid & 31;
    int s = blockIdx.x, b = blockIdx.y;
    int k0 = s * KSPL;
    int wc0 = (wid & 3) * 32, wn0 = (wid >> 2) * 64;
    int lrow = lane >> 2, lcol = (lane & 3) * 2;

    const __half* qh = g_qhi + (size_t)b*CC*NPAD + k0;
    const __half* ql = g_qlo + (size_t)b*CC*NPAD + k0;
    const __half* kh = g_khi + (size_t)b*CC*NPAD + k0;
    const __half* kl = g_klo + (size_t)b*CC*NPAD + k0;

    auto prefetch = [&](int ch) {
        u32 dst = sb + (ch % 3) * LSTAGE;
        cpa_tile64(dst + 0*LTILE, qh + ch*64, NPAD);
        cpa_tile64(dst + 1*LTILE, ql + ch*64, NPAD);
        cpa_tile64(dst + 2*LTILE, kh + ch*64, NPAD);
        cpa_tile64(dst + 3*LTILE, kl + ch*64, NPAD);
        CP_COMMIT();
    };
    prefetch(0); prefetch(1); prefetch(2);

    float acc[2][8][4];
    #pragma unroll
    for (int i = 0; i < 2; i++)
        #pragma unroll
        for (int j = 0; j < 8; j++)
            #pragma unroll
            for (int q = 0; q < 4; q++) acc[i][j][q] = 0.f;

    u32 aoff = (u32)(wc0 + (lane & 15)) * 144 + ((lane >> 4) << 4);
    u32 boff = (u32)(wn0 + ((lane >> 4) << 3) + (lane & 7)) * 144 + (((lane >> 3) & 1) << 4);

    for (int ch = 0; ch < LNCH; ch++) {
        if (ch + 2 <= LNCH - 1)      { CP_WAIT(2); }
        else if (ch + 1 <= LNCH - 1) { CP_WAIT(1); }
        else                         { CP_WAIT(0); }
        __syncthreads();
        u32 st = sb + (ch % 3) * LSTAGE;
        gemm64_split(acc, st, st + LTILE, st + 2*LTILE, st + 3*LTILE, aoff, boff);
        __syncthreads();
        if (ch + 3 < LNCH) prefetch(ch + 3);
    }

    float* dst = g_part + ((size_t)(b*SPLIT + s))*CC*CC;
    #pragma unroll
    for (int mt = 0; mt < 2; mt++)
        #pragma unroll
        for (int hr = 0; hr < 2; hr++) {
            int c = wc0 + mt*16 + hr*8 + lrow;
            #pragma unroll
            for (int nt = 0; nt < 8; nt++) {
                int d = wn0 + nt*8 + lcol;
                *(float2*)(dst + (size_t)c*CC + d) =
                    make_float2(acc[mt][nt][hr*2+0], acc[mt][nt][hr*2+1]);
            }
        }
}

// ---------------- K4: reduce + softmax -> attn hi ------------------------------
__global__ void softmax_kernel()
{
    int c = blockIdx.x, b = blockIdx.y;
    int d = threadIdx.x;
    const float* p = g_part + ((size_t)b*SPLIT*CC + c)*CC + d;
    float sum = 0.f;
    #pragma unroll
    for (int s = 0; s < SPLIT; s++) sum += p[(size_t)s*CC*CC];

    __shared__ float rbuf[4], sbuf[4];
    float mx = sum;
    #pragma unroll
    for (int o = 16; o; o >>= 1) mx = fmaxf(mx, __shfl_xor_sync(0xffffffffu, mx, o));
    if ((d & 31) == 0) rbuf[d >> 5] = mx;
    __syncthreads();
    mx = fmaxf(fmaxf(rbuf[0], rbuf[1]), fmaxf(rbuf[2], rbuf[3]));
    float e = expf(sum - mx);
    float tt = e;
    #pragma unroll
    for (int o = 16; o; o >>= 1) tt += __shfl_xor_sync(0xffffffffu, tt, o);
    if ((d & 31) == 0) sbuf[d >> 5] = tt;
    __syncthreads();
    tt = (sbuf[0] + sbuf[1]) + (sbuf[2] + sbuf[3]);
    g_ahi[((size_t)b*CC + c)*CC + d] = __float2half_rn(e / tt);
}

// ---------------- K5: out = attn @ v (hi only, 2-stage pipeline) ---------------
#define OSTAGE 36864
#define OUT_SMEM 73728

__global__ __launch_bounds__(256, 1) void out_kernel(float* __restrict__ out)
{
    extern __shared__ char smem[];
    u32 sb = smem_u32(smem);
    int tid = threadIdx.x, wid = tid >> 5, lane = tid & 31;
    int b = blockIdx.y, n0 = blockIdx.x * 128;
    int wc0 = (wid & 3) * 32, wn0 = (wid >> 2) * 64;
    int lrow = lane >> 2, lcol = (lane & 3) * 2;

    const __half* ah = g_ahi + (size_t)b*CC*CC;
    const __half* vh = g_vThi + ((size_t)b*NPAD + n0)*CC;

    #pragma unroll
    for (int ch = 0; ch < 2; ch++) {
        u32 dst = sb + ch * OSTAGE;
        cpa_tile64(dst,          ah + ch*64, CC);
        cpa_tile64(dst + LTILE,  vh + ch*64, CC);
        CP_COMMIT();
    }

    float acc[2][8][4];
    #pragma unroll
    for (int i = 0; i < 2; i++)
        #pragma unroll
        for (int j = 0; j < 8; j++)
            #pragma unroll
            for (int q = 0; q < 4; q++) acc[i][j][q] = 0.f;

    u32 aoff = (u32)(wc0 + (lane & 15)) * 144 + ((lane >> 4) << 4);
    u32 boff = (u32)(wn0 + ((lane >> 4) << 3) + (lane & 7)) * 144 + (((lane >> 3) & 1) << 4);

    #pragma unroll
    for (int ch = 0; ch < 2; ch++) {
        if (ch == 0) { CP_WAIT(1); } else { CP_WAIT(0); }
        __syncthreads();
        u32 st = sb + ch * OSTAGE;
        gemm64_one(acc, st, st + LTILE, aoff, boff);
    }

    #pragma unroll
    for (int mt = 0; mt < 2; mt++)
        #pragma unroll
        for (int hr = 0; hr < 2; hr++) {
            int c = wc0 + mt*16 + hr*8 + lrow;
            #pragma unroll
            for (int nt = 0; nt < 8; nt++) {
                int n = n0 + wn0 + nt*8 + lcol;
                if (n < NPT)
                    *(float2*)(out + ((size_t)b*CC + c)*NPT + n) =
                        make_float2(acc[mt][nt][hr*2+0], acc[mt][nt][hr*2+1]);
            }
        }
}

// ---------------- host entry ----------------------------------------------------
extern "C" void kernel_launch(void* const* d_in, const int* in_sizes, int n_in,
                              void* d_out, int out_size)
{
    (void)in_sizes; (void)n_in; (void)out_size;
    const float* PC = (const float*)d_in[0];
    const float* X  = (const float*)d_in[1];

    cudaFuncSetAttribute(proj_kernel,   cudaFuncAttributeMaxDynamicSharedMemorySize, PROJ_SMEM);
    cudaFuncSetAttribute(logits_kernel, cudaFuncAttributeMaxDynamicSharedMemorySize, LOG_SMEM);
    cudaFuncSetAttribute(out_kernel,    cudaFuncAttributeMaxDynamicSharedMemorySize, OUT_SMEM);

    setup_kernel<<<192, 256>>>(
        (const float*)d_in[2],  (const float*)d_in[3],  (const float*)d_in[4],
        (const float*)d_in[5],  (const float*)d_in[6],
        (const float*)d_in[7],  (const float*)d_in[8],  (const float*)d_in[9],
        (const float*)d_in[10], (const float*)d_in[11],
        (const float*)d_in[12], (const float*)d_in[13], (const float*)d_in[14],
        (const float*)d_in[15], (const float*)d_in[16],
        (const float*)d_in[17], (const float*)d_in[18],
        (const float*)d_in[19], (const float*)d_in[20]);

    transpose_kernel<<<dim3(NT_PROJ, BATCH), 256>>>(PC);
    proj_kernel<<<dim3(NT_PROJ, BATCH), 256, PROJ_SMEM>>>(X);
    logits_kernel<<<dim3(SPLIT, BATCH), 256, LOG_SMEM>>>();
    softmax_kernel<<<dim3(CC, BATCH), CC>>>();
    out_kernel<<<dim3(NT_OUT, BATCH), 256, OUT_SMEM>>>((float*)d_out);
}